// round 1
// baseline (speedup 1.0000x reference)
#include <cuda_runtime.h>
#include <math.h>

#define B_TOT   131072
#define NN      17          // num nodes
#define H       32          // hidden
#define EPS     1e-5f
#define D_IN    53          // H + 17 + 3 + 1
#define WPB     8           // warps per block
#define SPW     8           // samples per warp
// grid = B_TOT / (WPB*SPW) = 2048 blocks of 256 threads

// ---------------- scratch (device globals; no allocation allowed) ------------
__device__ float gH2[(size_t)B_TOT * NN * H];   // 285 MB staging of h2
__device__ float gSum[NN];
__device__ float gSq[NN];
__device__ float gA[NN];     // gamma*rsqrt(var+eps)/17
__device__ float gCbar;      // sum_n (beta - mean*A)/17

__device__ __forceinline__ float elu_f(float x) {
    return x > 0.f ? x : (expf(x) - 1.f);
}

// ---------------------------------------------------------------------------
__global__ void zero_stats_kernel() {
    int t = threadIdx.x;
    if (t < NN) { gSum[t] = 0.f; gSq[t] = 0.f; }
}

// ---------------------------------------------------------------------------
// Pass 1: per-sample GCN (2 layers), store h2 to gH2, accumulate BN stats.
// One warp per sample; lane = hidden index.
__global__ __launch_bounds__(256) void pass1_kernel(
    const float* __restrict__ x_str,   // [B,17,1]
    const float* __restrict__ adj,     // [B,17,17]
    const float* __restrict__ W1,      // [1,32]
    const float* __restrict__ b1,      // [32]
    const float* __restrict__ W2,      // [32,32]
    const float* __restrict__ b2)      // [32]
{
    __shared__ float adjS[WPB][NN * 20];   // support matrix, row stride 20
    __shared__ float bufS[WPB][NN * 36];   // agg staging, row stride 36 (16B aligned)
    __shared__ float dS[WPB][20];
    __shared__ float xS[WPB][20];
    __shared__ float sS[WPB][20];
    __shared__ float blkAcc[2 * NN];

    const int tid  = threadIdx.x;
    const int lane = tid & 31;
    const int w    = tid >> 5;

    if (tid < 2 * NN) blkAcc[tid] = 0.f;
    __syncthreads();

    const float w1l = W1[lane];
    const float b1l = b1[lane];
    const float b2l = b2[lane];
    float W2c[H];
    #pragma unroll
    for (int k = 0; k < H; k++) W2c[k] = W2[k * H + lane];

    float sumP[NN], sqP[NN];
    #pragma unroll
    for (int n = 0; n < NN; n++) { sumP[n] = 0.f; sqP[n] = 0.f; }

    float* aS = adjS[w];
    float* bS = bufS[w];
    float* dv = dS[w];
    float* xs = xS[w];
    float* ss = sS[w];

    const long base = ((long)blockIdx.x * WPB + w) * SPW;

    #pragma unroll 1
    for (int s = 0; s < SPW; s++) {
        const long b = base + s;
        const float* adjp = adj + b * (NN * NN);

        // load adj tile
        for (int idx = lane; idx < NN * NN; idx += 32) {
            int n = idx / NN, m = idx - n * NN;
            aS[n * 20 + m] = adjp[idx];
        }
        if (lane < NN) xs[lane] = x_str[b * NN + lane];
        __syncwarp();

        // degrees of A_hat = adj + I, d^-1/2
        if (lane < NN) {
            float dg = 1.0f;
            #pragma unroll
            for (int m = 0; m < NN; m++) dg += aS[lane * 20 + m];
            dv[lane] = dg > 0.f ? rsqrtf(dg) : 0.f;
        }
        __syncwarp();

        // support = D^-1/2 A_hat D^-1/2 in place
        for (int idx = lane; idx < NN * NN; idx += 32) {
            int n = idx / NN, m = idx - n * NN;
            float v = aS[n * 20 + m] + (n == m ? 1.f : 0.f);
            aS[n * 20 + m] = v * dv[n] * dv[m];
        }
        __syncwarp();

        // s = support @ x
        if (lane < NN) {
            float acc = 0.f;
            #pragma unroll
            for (int m = 0; m < NN; m++) acc += aS[lane * 20 + m] * xs[m];
            ss[lane] = acc;
        }
        __syncwarp();

        // h1[n] (this lane's hidden channel)
        float h1[NN];
        #pragma unroll
        for (int n = 0; n < NN; n++) h1[n] = elu_f(ss[n] * w1l + b1l);

        // agg = support @ h1  -> bufS
        #pragma unroll
        for (int n = 0; n < NN; n++) {
            float acc = 0.f;
            #pragma unroll
            for (int m = 0; m < NN; m++) acc += aS[n * 20 + m] * h1[m];
            bS[n * 36 + lane] = acc;
        }
        __syncwarp();

        // t = agg @ W2 + b2 ; h2 = elu(t) ; store + stats
        float* outp = gH2 + b * (NN * H);
        #pragma unroll
        for (int n = 0; n < NN; n++) {
            float acc = b2l;
            #pragma unroll
            for (int k4 = 0; k4 < 8; k4++) {
                float4 a4 = *reinterpret_cast<const float4*>(&bS[n * 36 + k4 * 4]);
                acc += a4.x * W2c[4 * k4 + 0];
                acc += a4.y * W2c[4 * k4 + 1];
                acc += a4.z * W2c[4 * k4 + 2];
                acc += a4.w * W2c[4 * k4 + 3];
            }
            float h2 = elu_f(acc);
            outp[n * H + lane] = h2;
            sumP[n] += h2;
            sqP[n]  += h2 * h2;
        }
        __syncwarp();
    }

    // warp butterfly reduce stats (over hidden lanes)
    #pragma unroll
    for (int n = 0; n < NN; n++) {
        #pragma unroll
        for (int off = 16; off; off >>= 1) {
            sumP[n] += __shfl_xor_sync(0xffffffffu, sumP[n], off);
            sqP[n]  += __shfl_xor_sync(0xffffffffu, sqP[n],  off);
        }
    }
    if (lane == 0) {
        #pragma unroll
        for (int n = 0; n < NN; n++) {
            atomicAdd(&blkAcc[n], sumP[n]);
            atomicAdd(&blkAcc[NN + n], sqP[n]);
        }
    }
    __syncthreads();
    if (tid < NN)           atomicAdd(&gSum[tid],      blkAcc[tid]);
    else if (tid < 2 * NN)  atomicAdd(&gSq[tid - NN],  blkAcc[tid]);
}

// ---------------------------------------------------------------------------
__global__ void finalize_kernel(const float* __restrict__ gamma,
                                const float* __restrict__ beta)
{
    int n = threadIdx.x;
    float Cl = 0.f;
    if (n < NN) {
        const float inv_cnt = 1.f / ((float)B_TOT * (float)H);
        float mean = gSum[n] * inv_cnt;
        float var  = gSq[n] * inv_cnt - mean * mean;
        float rs   = rsqrtf(var + EPS);
        float A    = gamma[n] * rs;
        float C    = beta[n] - mean * A;
        gA[n] = A * (1.f / 17.f);
        Cl    = C * (1.f / 17.f);
    }
    #pragma unroll
    for (int off = 16; off; off >>= 1) Cl += __shfl_xor_sync(0xffffffffu, Cl, off);
    if (n == 0) gCbar = Cl;
}

// ---------------------------------------------------------------------------
// Pass 2: BN-fold + node mean + MLP head. One warp per sample.
__global__ __launch_bounds__(256) void pass2_kernel(
    const float* __restrict__ x_raw,   // [B,17]
    const float* __restrict__ x_cov,   // [B,3]
    const float* __restrict__ age,     // [B,1]
    const float* __restrict__ Wr1,     // [53,64]
    const float* __restrict__ br1,     // [64]
    const float* __restrict__ Wr2,     // [64,32]
    const float* __restrict__ br2,     // [32]
    const float* __restrict__ Wr3,     // [32,1]
    const float* __restrict__ br3,     // [1]
    float* __restrict__ out)           // [B,1]
{
    __shared__ float Wr1s[D_IN * 64];
    __shared__ float Wr2s[64 * H];
    __shared__ float br1s[64], br2s[H], Wr3s[H];
    __shared__ float As[NN];
    __shared__ float combS[WPB][64];
    __shared__ float z1S[WPB][64];
    __shared__ float cbarS, br3s;

    const int tid = threadIdx.x;
    for (int i = tid; i < D_IN * 64; i += 256) Wr1s[i] = Wr1[i];
    for (int i = tid; i < 64 * H;  i += 256) Wr2s[i] = Wr2[i];
    if (tid < 64) br1s[tid] = br1[tid];
    if (tid < H)  { br2s[tid] = br2[tid]; Wr3s[tid] = Wr3[tid]; }
    if (tid < NN) As[tid] = gA[tid];
    if (tid == 0) { cbarS = gCbar; br3s = br3[0]; }
    __syncthreads();

    const int lane = tid & 31;
    const int w    = tid >> 5;
    float* comb = combS[w];
    float* z1   = z1S[w];
    const long base = ((long)blockIdx.x * WPB + w) * SPW;

    #pragma unroll 1
    for (int s = 0; s < SPW; s++) {
        const long b = base + s;
        const float* hp = gH2 + b * (NN * H);

        // graph_emb with BN folded in
        float ge = cbarS;
        #pragma unroll
        for (int n = 0; n < NN; n++) ge += As[n] * hp[n * H + lane];
        comb[lane] = ge;
        if (lane < NN) comb[H + lane] = x_raw[b * NN + lane];
        if (lane < 3)  comb[H + NN + lane] = x_cov[b * 3 + lane];
        if (lane == 0) comb[52] = age[b];
        __syncwarp();

        // layer 1: 53 -> 64, lane computes outputs lane and lane+32
        float a0 = br1s[lane], a1 = br1s[32 + lane];
        #pragma unroll
        for (int i = 0; i < D_IN; i++) {
            float c = comb[i];
            a0 += c * Wr1s[i * 64 + lane];
            a1 += c * Wr1s[i * 64 + 32 + lane];
        }
        z1[lane]      = fmaxf(a0, 0.f);
        z1[32 + lane] = fmaxf(a1, 0.f);
        __syncwarp();

        // layer 2: 64 -> 32
        float a2 = br2s[lane];
        #pragma unroll
        for (int i = 0; i < 64; i++) a2 += z1[i] * Wr2s[i * H + lane];
        a2 = fmaxf(a2, 0.f);

        // layer 3: 32 -> 1 (warp reduce)
        float z3 = a2 * Wr3s[lane];
        #pragma unroll
        for (int off = 16; off; off >>= 1) z3 += __shfl_xor_sync(0xffffffffu, z3, off);
        if (lane == 0) out[b] = 1.f / (1.f + expf(-(z3 + br3s)));
        __syncwarp();
    }
}

// ---------------------------------------------------------------------------
extern "C" void kernel_launch(void* const* d_in, const int* in_sizes, int n_in,
                              void* d_out, int out_size)
{
    const float* x_str = (const float*)d_in[0];
    const float* x_raw = (const float*)d_in[1];
    const float* adj   = (const float*)d_in[2];
    const float* x_cov = (const float*)d_in[3];
    const float* age   = (const float*)d_in[4];
    const float* W1    = (const float*)d_in[5];
    const float* b1    = (const float*)d_in[6];
    const float* W2    = (const float*)d_in[7];
    const float* b2    = (const float*)d_in[8];
    const float* gamma = (const float*)d_in[9];
    const float* beta  = (const float*)d_in[10];
    const float* Wr1   = (const float*)d_in[11];
    const float* br1   = (const float*)d_in[12];
    const float* Wr2   = (const float*)d_in[13];
    const float* br2   = (const float*)d_in[14];
    const float* Wr3   = (const float*)d_in[15];
    const float* br3   = (const float*)d_in[16];

    const int blocks = B_TOT / (WPB * SPW);   // 2048

    zero_stats_kernel<<<1, 32>>>();
    pass1_kernel<<<blocks, 256>>>(x_str, adj, W1, b1, W2, b2);
    finalize_kernel<<<1, 32>>>(gamma, beta);
    pass2_kernel<<<blocks, 256>>>(x_raw, x_cov, age,
                                  Wr1, br1, Wr2, br2, Wr3, br3,
                                  (float*)d_out);
}

// round 2
// speedup vs baseline: 1.1892x; 1.1892x over previous
#include <cuda_runtime.h>
#include <cuda_fp16.h>
#include <math.h>

#define B_TOT   131072
#define NN      17
#define H       32
#define EPS     1e-5f
#define D_IN    53
#define WPB     8           // warps per block (pass1)
#define SPW     8           // samples per warp (pass1)

// ---------------- scratch (device globals; no allocation allowed) ------------
__device__ __half gH2h[(size_t)B_TOT * NN * H];   // 142 MB fp16 staging of h2
__device__ float gSum[NN];
__device__ float gSq[NN];
__device__ float gA[NN];     // gamma*rsqrt(var+eps)/17
__device__ float gCbar;      // sum_n (beta - mean*A)/17

// ---------------- packed f32x2 helpers ---------------------------------------
typedef unsigned long long ull;

__device__ __forceinline__ ull pk2(float lo, float hi) {
    ull r; asm("mov.b64 %0,{%1,%2};" : "=l"(r) : "f"(lo), "f"(hi)); return r;
}
__device__ __forceinline__ void upk2(ull v, float& lo, float& hi) {
    asm("mov.b64 {%0,%1},%2;" : "=f"(lo), "=f"(hi) : "l"(v));
}
__device__ __forceinline__ void ffma2(ull& d, ull a, ull b) {
    asm("fma.rn.f32x2 %0,%1,%2,%0;" : "+l"(d) : "l"(a), "l"(b));
}

__device__ __forceinline__ float elu_f(float x) {
    // branchless: x>0 -> x ; x<=0 -> exp(x)-1  (exp(0)-1 = 0)
    return fmaxf(x, 0.f) + (__expf(fminf(x, 0.f)) - 1.f);
}

// ---------------------------------------------------------------------------
__global__ void zero_stats_kernel() {
    int t = threadIdx.x;
    if (t < NN) { gSum[t] = 0.f; gSq[t] = 0.f; }
}

// ---------------------------------------------------------------------------
// Pass 1: per-sample 2-layer GCN, h2 -> gH2h (fp16), BN stats accumulate.
// One warp per sample; lane = hidden index.
__global__ __launch_bounds__(256) void pass1_kernel(
    const float* __restrict__ x_str,   // [B,17,1]
    const float* __restrict__ adj,     // [B,17,17]
    const float* __restrict__ W1,      // [1,32]
    const float* __restrict__ b1,      // [32]
    const float* __restrict__ W2,      // [32,32]
    const float* __restrict__ b2)      // [32]
{
    __shared__ float adjS[WPB][NN * 20];   // support matrix, row stride 20 (80B, 16B aligned)
    __shared__ float bufS[WPB][NN * 36];   // agg staging, row stride 36 (144B, 16B aligned)
    __shared__ float dS[WPB][20];
    __shared__ float xS[WPB][20];
    __shared__ float sS[WPB][20];
    __shared__ float blkAcc[2 * NN];

    const int tid  = threadIdx.x;
    const int lane = tid & 31;
    const int w    = tid >> 5;

    if (tid < 2 * NN) blkAcc[tid] = 0.f;
    __syncthreads();

    const float w1l = W1[lane];
    const float b1l = b1[lane];
    const float b2l = b2[lane];

    // W2 column for this lane, packed over k-pairs: W2p[j] = (W2[2j][lane], W2[2j+1][lane])
    ull W2p[16];
    #pragma unroll
    for (int j = 0; j < 16; j++)
        W2p[j] = pk2(W2[(2 * j) * H + lane], W2[(2 * j + 1) * H + lane]);

    float sumP[NN], sqP[NN];
    #pragma unroll
    for (int n = 0; n < NN; n++) { sumP[n] = 0.f; sqP[n] = 0.f; }

    float* aS = adjS[w];
    float* bS = bufS[w];
    float* dv = dS[w];
    float* xs = xS[w];
    float* ss = sS[w];

    const long base = ((long)blockIdx.x * WPB + w) * SPW;

    #pragma unroll 1
    for (int s = 0; s < SPW; s++) {
        const long b = base + s;
        const float* adjp = adj + b * (NN * NN);

        // load adj tile (coalesced)
        for (int idx = lane; idx < NN * NN; idx += 32) {
            int n = idx / NN, m = idx - n * NN;
            aS[n * 20 + m] = adjp[idx];
        }
        if (lane < NN) xs[lane] = x_str[b * NN + lane];
        __syncwarp();

        // degrees of A_hat = adj + I, d^-1/2
        if (lane < NN) {
            float dg = 1.0f;
            #pragma unroll
            for (int m = 0; m < NN; m++) dg += aS[lane * 20 + m];
            dv[lane] = dg > 0.f ? rsqrtf(dg) : 0.f;
        }
        __syncwarp();

        // support = D^-1/2 (adj+I) D^-1/2 in place
        for (int idx = lane; idx < NN * NN; idx += 32) {
            int n = idx / NN, m = idx - n * NN;
            float v = aS[n * 20 + m] + (n == m ? 1.f : 0.f);
            aS[n * 20 + m] = v * dv[n] * dv[m];
        }
        __syncwarp();

        // s = support @ x
        if (lane < NN) {
            float acc = 0.f;
            #pragma unroll
            for (int m = 0; m < NN; m++) acc += aS[lane * 20 + m] * xs[m];
            ss[lane] = acc;
        }
        __syncwarp();

        // h1[m] for this lane's hidden channel; pack pairs for f32x2
        float h1[NN];
        #pragma unroll
        for (int m = 0; m < NN; m++) h1[m] = elu_f(ss[m] * w1l + b1l);
        ull h1p[8];
        #pragma unroll
        for (int j = 0; j < 8; j++) h1p[j] = pk2(h1[2 * j], h1[2 * j + 1]);
        const float h1_16 = h1[16];

        // agg = support @ h1  -> bufS   (f32x2 over m-pairs)
        #pragma unroll
        for (int n = 0; n < NN; n++) {
            const ulonglong2* av = reinterpret_cast<const ulonglong2*>(&aS[n * 20]);
            ull acc2 = 0ull;
            #pragma unroll
            for (int q = 0; q < 4; q++) {
                ulonglong2 v = av[q];
                ffma2(acc2, v.x, h1p[2 * q]);
                ffma2(acc2, v.y, h1p[2 * q + 1]);
            }
            float alo, ahi; upk2(acc2, alo, ahi);
            bS[n * 36 + lane] = alo + ahi + aS[n * 20 + 16] * h1_16;
        }
        __syncwarp();

        // t = agg @ W2 + b2 ; h2 = elu(t) ; fp16 store + stats (f32x2 over k-pairs)
        __half* outp = gH2h + b * (NN * H);
        #pragma unroll
        for (int n = 0; n < NN; n++) {
            const ulonglong2* bv = reinterpret_cast<const ulonglong2*>(&bS[n * 36]);
            ull acc2 = 0ull;
            #pragma unroll
            for (int q = 0; q < 8; q++) {
                ulonglong2 v = bv[q];                 // agg[4q..4q+3] (broadcast)
                ffma2(acc2, v.x, W2p[2 * q]);
                ffma2(acc2, v.y, W2p[2 * q + 1]);
            }
            float tlo, thi; upk2(acc2, tlo, thi);
            float h2 = elu_f(tlo + thi + b2l);
            outp[n * H + lane] = __float2half(h2);
            sumP[n] += h2;
            sqP[n]  += h2 * h2;
        }
        __syncwarp();
    }

    // warp butterfly reduce stats
    #pragma unroll
    for (int n = 0; n < NN; n++) {
        #pragma unroll
        for (int off = 16; off; off >>= 1) {
            sumP[n] += __shfl_xor_sync(0xffffffffu, sumP[n], off);
            sqP[n]  += __shfl_xor_sync(0xffffffffu, sqP[n],  off);
        }
    }
    if (lane == 0) {
        #pragma unroll
        for (int n = 0; n < NN; n++) {
            atomicAdd(&blkAcc[n], sumP[n]);
            atomicAdd(&blkAcc[NN + n], sqP[n]);
        }
    }
    __syncthreads();
    if (tid < NN)           atomicAdd(&gSum[tid],      blkAcc[tid]);
    else if (tid < 2 * NN)  atomicAdd(&gSq[tid - NN],  blkAcc[tid]);
}

// ---------------------------------------------------------------------------
__global__ void finalize_kernel(const float* __restrict__ gamma,
                                const float* __restrict__ beta)
{
    int n = threadIdx.x;
    float Cl = 0.f;
    if (n < NN) {
        const float inv_cnt = 1.f / ((float)B_TOT * (float)H);
        float mean = gSum[n] * inv_cnt;
        float var  = gSq[n] * inv_cnt - mean * mean;
        float rs   = rsqrtf(var + EPS);
        float A    = gamma[n] * rs;
        float C    = beta[n] - mean * A;
        gA[n] = A * (1.f / 17.f);
        Cl    = C * (1.f / 17.f);
    }
    #pragma unroll
    for (int off = 16; off; off >>= 1) Cl += __shfl_xor_sync(0xffffffffu, Cl, off);
    if (n == 0) gCbar = Cl;
}

// ---------------------------------------------------------------------------
// Pass 2: BN-fold + node mean + MLP head.
// Phase A (lane=h): compute comb[53] per sample into shared.
// Phase B (lane=sample): full MLP per lane with broadcast weight loads + f32x2.
#define P2_WARPS 8
#define P2_SMEM_FLOATS (3392 + 2048 + P2_WARPS*32*53 + 64 + 32 + 32 + 17 + 2)

__global__ __launch_bounds__(256) void pass2_kernel(
    const float* __restrict__ x_raw,   // [B,17]
    const float* __restrict__ x_cov,   // [B,3]
    const float* __restrict__ age,     // [B,1]
    const float* __restrict__ Wr1,     // [53,64]
    const float* __restrict__ br1,     // [64]
    const float* __restrict__ Wr2,     // [64,32]
    const float* __restrict__ br2,     // [32]
    const float* __restrict__ Wr3,     // [32,1]
    const float* __restrict__ br3,     // [1]
    float* __restrict__ out)           // [B,1]
{
    extern __shared__ float sm[];
    float* Wr1s  = sm;                       // 3392  (rows of 64, 16B aligned)
    float* Wr2s  = Wr1s + 3392;              // 2048  (rows of 32, 16B aligned)
    float* combS = Wr2s + 2048;              // 8*32*53
    float* br1s  = combS + P2_WARPS * 32 * 53; // 64 (8B aligned: offset 19008 floats)
    float* br2s  = br1s + 64;                // 32
    float* wr3s  = br2s + 32;                // 32
    float* As_   = wr3s + 32;                // 17
    float* misc  = As_ + 17;                 // [0]=cbar [1]=br3

    const int tid = threadIdx.x;
    for (int i = tid; i < 3392; i += 256) Wr1s[i] = Wr1[i];
    for (int i = tid; i < 2048; i += 256) Wr2s[i] = Wr2[i];
    if (tid < 64) br1s[tid] = br1[tid];
    if (tid < 32) { br2s[tid] = br2[tid]; wr3s[tid] = Wr3[tid]; }
    if (tid < NN) As_[tid] = gA[tid];
    if (tid == 0) { misc[0] = gCbar; misc[1] = br3[0]; }
    __syncthreads();

    const int lane = tid & 31;
    const int w    = tid >> 5;
    float* comb = combS + w * (32 * 53);
    const long base = ((long)blockIdx.x * P2_WARPS + w) * 32;

    float As_r[NN];
    #pragma unroll
    for (int n = 0; n < NN; n++) As_r[n] = As_[n];
    const float cbar = misc[0];

    // ---- Phase A: build comb rows for this warp's 32 samples ----
    #pragma unroll 1
    for (int s2 = 0; s2 < 32; s2++) {
        const long b = base + s2;
        const __half* hp = gH2h + b * (NN * H);
        float ge = cbar;
        #pragma unroll
        for (int n = 0; n < NN; n++)
            ge += As_r[n] * __half2float(hp[n * H + lane]);
        comb[s2 * 53 + lane] = ge;
        if (lane < NN)      comb[s2 * 53 + 32 + lane] = x_raw[b * NN + lane];
        else if (lane < 20) comb[s2 * 53 + 32 + lane] = x_cov[b * 3 + (lane - NN)];
        else if (lane == 20) comb[s2 * 53 + 52] = age[b];
    }
    __syncwarp();

    // ---- Phase B: lane = sample ----
    const long b = base + lane;
    const float* cl = comb + lane * 53;      // stride 53 across lanes: conflict-free

    // layer 1: 53 -> 64 (packed accumulators over output pairs)
    ull z1a[32];
    const ull* b1u = reinterpret_cast<const ull*>(br1s);
    #pragma unroll
    for (int j = 0; j < 32; j++) z1a[j] = b1u[j];
    #pragma unroll 1
    for (int i = 0; i < D_IN; i++) {
        float ci = cl[i];
        ull c2 = pk2(ci, ci);
        const ulonglong2* wv = reinterpret_cast<const ulonglong2*>(&Wr1s[i * 64]);
        #pragma unroll
        for (int q = 0; q < 16; q++) {
            ulonglong2 v = wv[q];
            ffma2(z1a[2 * q],     c2, v.x);
            ffma2(z1a[2 * q + 1], c2, v.y);
        }
    }
    float z1[64];
    #pragma unroll
    for (int j = 0; j < 32; j++) {
        float lo, hi; upk2(z1a[j], lo, hi);
        z1[2 * j]     = fmaxf(lo, 0.f);
        z1[2 * j + 1] = fmaxf(hi, 0.f);
    }

    // layer 2: 64 -> 32
    ull z2a[16];
    const ull* b2u = reinterpret_cast<const ull*>(br2s);
    #pragma unroll
    for (int j = 0; j < 16; j++) z2a[j] = b2u[j];
    #pragma unroll 4
    for (int i = 0; i < 64; i++) {
        ull c2 = pk2(z1[i], z1[i]);
        const ulonglong2* wv = reinterpret_cast<const ulonglong2*>(&Wr2s[i * 32]);
        #pragma unroll
        for (int q = 0; q < 8; q++) {
            ulonglong2 v = wv[q];
            ffma2(z2a[2 * q],     c2, v.x);
            ffma2(z2a[2 * q + 1], c2, v.y);
        }
    }

    // layer 3: 32 -> 1
    float acc = misc[1];
    #pragma unroll
    for (int j = 0; j < 16; j++) {
        float lo, hi; upk2(z2a[j], lo, hi);
        acc += fmaxf(lo, 0.f) * wr3s[2 * j];
        acc += fmaxf(hi, 0.f) * wr3s[2 * j + 1];
    }
    out[b] = 1.f / (1.f + expf(-acc));
}

// ---------------------------------------------------------------------------
extern "C" void kernel_launch(void* const* d_in, const int* in_sizes, int n_in,
                              void* d_out, int out_size)
{
    const float* x_str = (const float*)d_in[0];
    const float* x_raw = (const float*)d_in[1];
    const float* adj   = (const float*)d_in[2];
    const float* x_cov = (const float*)d_in[3];
    const float* age   = (const float*)d_in[4];
    const float* W1    = (const float*)d_in[5];
    const float* b1    = (const float*)d_in[6];
    const float* W2    = (const float*)d_in[7];
    const float* b2    = (const float*)d_in[8];
    const float* gamma = (const float*)d_in[9];
    const float* beta  = (const float*)d_in[10];
    const float* Wr1   = (const float*)d_in[11];
    const float* br1   = (const float*)d_in[12];
    const float* Wr2   = (const float*)d_in[13];
    const float* br2   = (const float*)d_in[14];
    const float* Wr3   = (const float*)d_in[15];
    const float* br3   = (const float*)d_in[16];

    const int blocks1 = B_TOT / (WPB * SPW);        // 2048
    const int blocks2 = B_TOT / (P2_WARPS * 32);    // 512
    const int smem2   = P2_SMEM_FLOATS * 4;         // ~76.6 KB

    static int attr_done = 0;
    if (!attr_done) {
        cudaFuncSetAttribute(pass2_kernel,
                             cudaFuncAttributeMaxDynamicSharedMemorySize, smem2);
        attr_done = 1;
    }

    zero_stats_kernel<<<1, 32>>>();
    pass1_kernel<<<blocks1, 256>>>(x_str, adj, W1, b1, W2, b2);
    finalize_kernel<<<1, 32>>>(gamma, beta);
    pass2_kernel<<<blocks2, 256, smem2>>>(x_raw, x_cov, age,
                                          Wr1, br1, Wr2, br2, Wr3, br3,
                                          (float*)d_out);
}